// round 7
// baseline (speedup 1.0000x reference)
#include <cuda_runtime.h>
#include <cuda_fp16.h>
#include <math.h>
#include <float.h>

#define NN 50000
#define EE 800000
#define ET (EE + NN)

// ---------------- scratch ---------------------------------------------------
__device__ __half g_h1[NN * 128];    // fp16 projections (gather-heavy)
__device__ __half g_h2[NN * 128];
__device__ float  g_agg1[NN * 128];  // layer-1 output (GEMM input) stays fp32
__device__ float  g_as1[NN * 4];
__device__ float  g_ad1[NN * 4];
__device__ float  g_as2[NN];
__device__ float  g_ad2[NN];
__device__ int    g_deg[NN];
__device__ int    g_rowptr[NN + 1];
__device__ int    g_fill[NN];
__device__ int    g_col[ET];

__device__ __forceinline__ float lrelu(float x) { return x > 0.f ? x : 0.2f * x; }
__device__ __forceinline__ float elu(float x)   { return x > 0.f ? x : expm1f(x); }

// ---------------- CSR build -------------------------------------------------
__global__ void k_zero() {
    int i = blockIdx.x * blockDim.x + threadIdx.x;
    if (i < NN) g_deg[i] = 0;
}

__global__ void k_count(const int* __restrict__ ei) {
    int e = blockIdx.x * blockDim.x + threadIdx.x;
    if (e >= ET) return;
    int d = (e < EE) ? ei[EE + e] : (e - EE);
    atomicAdd(&g_deg[d], 1);
}

// one block, 1024 threads: chunked serial sums + block scan + writeback
__global__ void k_scan() {
    __shared__ int bs[1024];
    const int CH = (NN + 1023) / 1024;   // 49
    int t = threadIdx.x;
    int base = t * CH;
    int lim = min(base + CH, NN);

    int s = 0;
    for (int i = base; i < lim; i++) s += g_deg[i];
    bs[t] = s;
    __syncthreads();
#pragma unroll
    for (int off = 1; off < 1024; off <<= 1) {
        int v = (t >= off) ? bs[t - off] : 0;
        __syncthreads();
        bs[t] += v;
        __syncthreads();
    }
    int run = (t == 0) ? 0 : bs[t - 1];
    for (int i = base; i < lim; i++) {
        int d = g_deg[i];
        g_fill[i] = run;
        run += d;
        g_rowptr[i + 1] = run;
    }
    if (t == 0) g_rowptr[0] = 0;
}

__global__ void k_fill(const int* __restrict__ ei) {
    int e = blockIdx.x * blockDim.x + threadIdx.x;
    if (e >= ET) return;
    int s, d;
    if (e < EE) { s = ei[e]; d = ei[EE + e]; } else { s = e - EE; d = s; }
    int pos = atomicAdd(&g_fill[d], 1);
    g_col[pos] = s;
}

// ---------------- GEMM [NN,128]@[128,128], scalar FFMA, fp16 H store --------
// LAYER 0: X = x (arg), H = g_h1, alpha -> g_as1/g_ad1 (HEADS=4)
// LAYER 1: X = g_agg1,  H = g_h2, alpha -> g_as2/g_ad2 (HEADS=1)
template <int LAYER>
__global__ void __launch_bounds__(256) k_gemm(const float* __restrict__ Xext,
                       const float* __restrict__ W,
                       const float* __restrict__ asrc,
                       const float* __restrict__ adst) {
    const float* __restrict__ X = (LAYER == 0) ? Xext : g_agg1;
    __half* __restrict__ H = (LAYER == 0) ? g_h1 : g_h2;

    __shared__ float xs[64][128];
    int row0 = blockIdx.x * 64;

    for (int i = threadIdx.x; i < 64 * 32; i += 256) {
        int r = i >> 5, c4 = i & 31;
        int row = row0 + r;
        float4 v = make_float4(0.f, 0.f, 0.f, 0.f);
        if (row < NN) v = ((const float4*)X)[row * 32 + c4];
        *(float4*)(&xs[r][c4 * 4]) = v;
    }
    __syncthreads();

    int tc = threadIdx.x & 31;   // 4-col group
    int tr = threadIdx.x >> 5;   // warp: rows tr*8 .. tr*8+7
    float acc[8][4];
#pragma unroll
    for (int r = 0; r < 8; r++)
#pragma unroll
        for (int j = 0; j < 4; j++) acc[r][j] = 0.f;

#pragma unroll 8
    for (int k = 0; k < 128; k++) {
        float4 w = ((const float4*)W)[k * 32 + tc];
#pragma unroll
        for (int r = 0; r < 8; r++) {
            float xv = xs[tr * 8 + r][k];
            acc[r][0] += xv * w.x;
            acc[r][1] += xv * w.y;
            acc[r][2] += xv * w.z;
            acc[r][3] += xv * w.w;
        }
    }

    float4 av = ((const float4*)asrc)[tc];
    float4 dv = ((const float4*)adst)[tc];

#pragma unroll
    for (int r = 0; r < 8; r++) {
        int row = row0 + tr * 8 + r;
        if (row >= NN) continue;
        __half2 p0 = __floats2half2_rn(acc[r][0], acc[r][1]);
        __half2 p1 = __floats2half2_rn(acc[r][2], acc[r][3]);
        ((__half2*)H)[row * 64 + tc * 2]     = p0;
        ((__half2*)H)[row * 64 + tc * 2 + 1] = p1;

        float s = acc[r][0] * av.x + acc[r][1] * av.y + acc[r][2] * av.z + acc[r][3] * av.w;
        float d = acc[r][0] * dv.x + acc[r][1] * dv.y + acc[r][2] * dv.z + acc[r][3] * dv.w;
        if (LAYER == 0) {
#pragma unroll
            for (int off = 4; off; off >>= 1) {
                s += __shfl_xor_sync(0xffffffffu, s, off);
                d += __shfl_xor_sync(0xffffffffu, d, off);
            }
            if ((tc & 7) == 0) {
                g_as1[row * 4 + (tc >> 3)] = s;
                g_ad1[row * 4 + (tc >> 3)] = d;
            }
        } else {
#pragma unroll
            for (int off = 16; off; off >>= 1) {
                s += __shfl_xor_sync(0xffffffffu, s, off);
                d += __shfl_xor_sync(0xffffffffu, d, off);
            }
            if (tc == 0) { g_as2[row] = s; g_ad2[row] = d; }
        }
    }
}

// ---------------- fused attention + aggregation, layer 1 (4 heads) ----------
// one warp per destination node; lane owns 4 channels (head = lane>>3)
__global__ void k_node1(const float* __restrict__ b1) {
    int w = (blockIdx.x * blockDim.x + threadIdx.x) >> 5;
    int lane = threadIdx.x & 31;
    if (w >= NN) return;
    int beg = g_rowptr[w], end = g_rowptr[w + 1];

    float4 ad = ((const float4*)g_ad1)[w];

    float4 mx = make_float4(-FLT_MAX, -FLT_MAX, -FLT_MAX, -FLT_MAX);
    for (int i = beg + lane; i < end; i += 32) {
        int s = g_col[i];
        float4 a = ((const float4*)g_as1)[s];
        mx.x = fmaxf(mx.x, lrelu(a.x + ad.x));
        mx.y = fmaxf(mx.y, lrelu(a.y + ad.y));
        mx.z = fmaxf(mx.z, lrelu(a.z + ad.z));
        mx.w = fmaxf(mx.w, lrelu(a.w + ad.w));
    }
#pragma unroll
    for (int off = 16; off; off >>= 1) {
        mx.x = fmaxf(mx.x, __shfl_xor_sync(0xffffffffu, mx.x, off));
        mx.y = fmaxf(mx.y, __shfl_xor_sync(0xffffffffu, mx.y, off));
        mx.z = fmaxf(mx.z, __shfl_xor_sync(0xffffffffu, mx.z, off));
        mx.w = fmaxf(mx.w, __shfl_xor_sync(0xffffffffu, mx.w, off));
    }

    int hd = lane >> 3;
    float mh  = (hd == 0) ? mx.x : (hd == 1) ? mx.y : (hd == 2) ? mx.z : mx.w;
    float adh = (hd == 0) ? ad.x : (hd == 1) ? ad.y : (hd == 2) ? ad.z : ad.w;

    float ws = 0.f;
    float4 acc = make_float4(0.f, 0.f, 0.f, 0.f);
    for (int i = beg; i < end; i++) {
        int s = g_col[i];
        float a = g_as1[s * 4 + hd];
        float wt = __expf(lrelu(a + adh) - mh);
        ws += wt;
        uint2 raw = ((const uint2*)g_h1)[s * 32 + lane];   // 4 halves
        float2 f01 = __half22float2(*reinterpret_cast<__half2*>(&raw.x));
        float2 f23 = __half22float2(*reinterpret_cast<__half2*>(&raw.y));
        acc.x += wt * f01.x;
        acc.y += wt * f01.y;
        acc.z += wt * f23.x;
        acc.w += wt * f23.y;
    }
    float inv = 1.f / (ws + 1e-16f);
    float4 bv = ((const float4*)b1)[lane];
    float4 o;
    o.x = elu(acc.x * inv + bv.x);
    o.y = elu(acc.y * inv + bv.y);
    o.z = elu(acc.z * inv + bv.z);
    o.w = elu(acc.w * inv + bv.w);
    ((float4*)g_agg1)[w * 32 + lane] = o;
}

// ---------------- fused attention + aggregation, layer 2 (1 head) -----------
__global__ void k_node2(const float* __restrict__ b2, float* __restrict__ out) {
    int w = (blockIdx.x * blockDim.x + threadIdx.x) >> 5;
    int lane = threadIdx.x & 31;
    if (w >= NN) return;
    int beg = g_rowptr[w], end = g_rowptr[w + 1];

    float adv = g_ad2[w];

    float mx = -FLT_MAX;
    for (int i = beg + lane; i < end; i += 32) {
        int s = g_col[i];
        mx = fmaxf(mx, lrelu(g_as2[s] + adv));
    }
#pragma unroll
    for (int off = 16; off; off >>= 1)
        mx = fmaxf(mx, __shfl_xor_sync(0xffffffffu, mx, off));

    float ws = 0.f;
    float4 acc = make_float4(0.f, 0.f, 0.f, 0.f);
    for (int i = beg; i < end; i++) {
        int s = g_col[i];
        float wt = __expf(lrelu(g_as2[s] + adv) - mx);
        ws += wt;
        uint2 raw = ((const uint2*)g_h2)[s * 32 + lane];
        float2 f01 = __half22float2(*reinterpret_cast<__half2*>(&raw.x));
        float2 f23 = __half22float2(*reinterpret_cast<__half2*>(&raw.y));
        acc.x += wt * f01.x;
        acc.y += wt * f01.y;
        acc.z += wt * f23.x;
        acc.w += wt * f23.y;
    }
    float inv = 1.f / (ws + 1e-16f);
    float4 bv = ((const float4*)b2)[lane];
    float4 o;
    o.x = elu(acc.x * inv + bv.x);
    o.y = elu(acc.y * inv + bv.y);
    o.z = elu(acc.z * inv + bv.z);
    o.w = elu(acc.w * inv + bv.w);
    ((float4*)out)[w * 32 + lane] = o;
}

// ---------------- host launch ------------------------------------------------
extern "C" void kernel_launch(void* const* d_in, const int* in_sizes, int n_in,
                              void* d_out, int out_size) {
    const float* x    = (const float*)d_in[0];
    const int*   ei   = (const int*)  d_in[1];
    const float* W1   = (const float*)d_in[2];
    const float* a_s1 = (const float*)d_in[3];
    const float* a_d1 = (const float*)d_in[4];
    const float* b1   = (const float*)d_in[5];
    const float* W2   = (const float*)d_in[6];
    const float* a_s2 = (const float*)d_in[7];
    const float* a_d2 = (const float*)d_in[8];
    const float* b2   = (const float*)d_in[9];
    float* out = (float*)d_out;

    const int EB = (ET + 255) / 256;
    const int NB = (NN + 255) / 256;
    const int WARPB = (NN * 32 + 255) / 256;

    // CSR build (shared by both layers)
    k_zero<<<NB, 256>>>();
    k_count<<<EB, 256>>>(ei);
    k_scan<<<1, 1024>>>();
    k_fill<<<EB, 256>>>(ei);

    // layer 1
    k_gemm<0><<<(NN + 63) / 64, 256>>>(x, W1, a_s1, a_d1);
    k_node1<<<WARPB, 256>>>(b1);

    // layer 2
    k_gemm<1><<<(NN + 63) / 64, 256>>>(nullptr, W2, a_s2, a_d2);
    k_node2<<<WARPB, 256>>>(b2, out);
}

// round 8
// speedup vs baseline: 1.3101x; 1.3101x over previous
#include <cuda_runtime.h>
#include <cuda_fp16.h>
#include <math.h>
#include <float.h>

#define NN 50000
#define EE 800000
#define ET (EE + NN)
#define SCAN_B 49   // ceil(50000/1024)

// ---------------- scratch ---------------------------------------------------
__device__ __half g_h1[NN * 128];    // fp16 projections (gather-heavy)
__device__ __half g_h2[NN * 128];
__device__ float  g_agg1[NN * 128];  // layer-1 output (GEMM input) stays fp32
__device__ float  g_as1[NN * 4];
__device__ float  g_ad1[NN * 4];
__device__ float  g_as2[NN];
__device__ float  g_ad2[NN];
__device__ int    g_deg[NN];
__device__ int    g_scan[SCAN_B * 1024];
__device__ int    g_bsum[SCAN_B];
__device__ int    g_boff[SCAN_B];
__device__ int    g_rowptr[NN + 1];
__device__ int    g_fill[NN];
__device__ int    g_col[ET];

__device__ __forceinline__ float lrelu(float x) { return x > 0.f ? x : 0.2f * x; }
__device__ __forceinline__ float elu(float x)   { return x > 0.f ? x : expm1f(x); }

// ---------------- CSR build -------------------------------------------------
__global__ void k_zero() {
    int i = blockIdx.x * blockDim.x + threadIdx.x;
    if (i < NN) g_deg[i] = 0;
}

__global__ void k_count(const int* __restrict__ ei) {
    int e = blockIdx.x * blockDim.x + threadIdx.x;
    if (e >= ET) return;
    int d = (e < EE) ? ei[EE + e] : (e - EE);
    atomicAdd(&g_deg[d], 1);
}

__global__ void k_scan_part() {
    __shared__ int sh[1024];
    int tid = threadIdx.x;
    int i = blockIdx.x * 1024 + tid;
    int v = (i < NN) ? g_deg[i] : 0;
    sh[tid] = v;
    __syncthreads();
#pragma unroll
    for (int off = 1; off < 1024; off <<= 1) {
        int t = (tid >= off) ? sh[tid - off] : 0;
        __syncthreads();
        sh[tid] += t;
        __syncthreads();
    }
    g_scan[i] = sh[tid];
    if (tid == 1023) g_bsum[blockIdx.x] = sh[tid];
}

__global__ void k_scan_top() {
    if (threadIdx.x == 0) {
        int s = 0;
        for (int b = 0; b < SCAN_B; b++) { int t = g_bsum[b]; g_boff[b] = s; s += t; }
    }
}

__global__ void k_rowptr() {
    int i = blockIdx.x * blockDim.x + threadIdx.x;
    if (i >= NN) return;
    int incl = g_scan[i] + g_boff[i >> 10];
    g_rowptr[i + 1] = incl;
    g_fill[i] = incl - g_deg[i];
    if (i == 0) g_rowptr[0] = 0;
}

__global__ void k_fill(const int* __restrict__ ei) {
    int e = blockIdx.x * blockDim.x + threadIdx.x;
    if (e >= ET) return;
    int s, d;
    if (e < EE) { s = ei[e]; d = ei[EE + e]; } else { s = e - EE; d = s; }
    int pos = atomicAdd(&g_fill[d], 1);
    g_col[pos] = s;
}

// ---------------- GEMM [NN,128]@[128,128], scalar FFMA, fp16 H store --------
// LAYER 0: X = x (arg), H = g_h1, alpha -> g_as1/g_ad1 (HEADS=4)
// LAYER 1: X = g_agg1,  H = g_h2, alpha -> g_as2/g_ad2 (HEADS=1)
template <int LAYER>
__global__ void __launch_bounds__(256) k_gemm(const float* __restrict__ Xext,
                       const float* __restrict__ W,
                       const float* __restrict__ asrc,
                       const float* __restrict__ adst) {
    const float* __restrict__ X = (LAYER == 0) ? Xext : g_agg1;
    __half* __restrict__ H = (LAYER == 0) ? g_h1 : g_h2;

    __shared__ float xs[64][128];
    int row0 = blockIdx.x * 64;

    for (int i = threadIdx.x; i < 64 * 32; i += 256) {
        int r = i >> 5, c4 = i & 31;
        int row = row0 + r;
        float4 v = make_float4(0.f, 0.f, 0.f, 0.f);
        if (row < NN) v = ((const float4*)X)[row * 32 + c4];
        *(float4*)(&xs[r][c4 * 4]) = v;
    }
    __syncthreads();

    int tc = threadIdx.x & 31;   // 4-col group
    int tr = threadIdx.x >> 5;   // warp: rows tr*8 .. tr*8+7
    float acc[8][4];
#pragma unroll
    for (int r = 0; r < 8; r++)
#pragma unroll
        for (int j = 0; j < 4; j++) acc[r][j] = 0.f;

#pragma unroll 8
    for (int k = 0; k < 128; k++) {
        float4 w = ((const float4*)W)[k * 32 + tc];
#pragma unroll
        for (int r = 0; r < 8; r++) {
            float xv = xs[tr * 8 + r][k];
            acc[r][0] += xv * w.x;
            acc[r][1] += xv * w.y;
            acc[r][2] += xv * w.z;
            acc[r][3] += xv * w.w;
        }
    }

    float4 av = ((const float4*)asrc)[tc];
    float4 dv = ((const float4*)adst)[tc];

#pragma unroll
    for (int r = 0; r < 8; r++) {
        int row = row0 + tr * 8 + r;
        if (row >= NN) continue;
        __half2 p0 = __floats2half2_rn(acc[r][0], acc[r][1]);
        __half2 p1 = __floats2half2_rn(acc[r][2], acc[r][3]);
        ((__half2*)H)[row * 64 + tc * 2]     = p0;
        ((__half2*)H)[row * 64 + tc * 2 + 1] = p1;

        float s = acc[r][0] * av.x + acc[r][1] * av.y + acc[r][2] * av.z + acc[r][3] * av.w;
        float d = acc[r][0] * dv.x + acc[r][1] * dv.y + acc[r][2] * dv.z + acc[r][3] * dv.w;
        if (LAYER == 0) {
#pragma unroll
            for (int off = 4; off; off >>= 1) {
                s += __shfl_xor_sync(0xffffffffu, s, off);
                d += __shfl_xor_sync(0xffffffffu, d, off);
            }
            if ((tc & 7) == 0) {
                g_as1[row * 4 + (tc >> 3)] = s;
                g_ad1[row * 4 + (tc >> 3)] = d;
            }
        } else {
#pragma unroll
            for (int off = 16; off; off >>= 1) {
                s += __shfl_xor_sync(0xffffffffu, s, off);
                d += __shfl_xor_sync(0xffffffffu, d, off);
            }
            if (tc == 0) { g_as2[row] = s; g_ad2[row] = d; }
        }
    }
}

// ---------------- fused attention + aggregation, layer 1 (4 heads) ----------
// one warp per destination node; lane owns 4 channels (head = lane>>3)
__global__ void k_node1(const float* __restrict__ b1) {
    int w = (blockIdx.x * blockDim.x + threadIdx.x) >> 5;
    int lane = threadIdx.x & 31;
    if (w >= NN) return;
    int beg = g_rowptr[w], end = g_rowptr[w + 1];

    float4 ad = ((const float4*)g_ad1)[w];

    float4 mx = make_float4(-FLT_MAX, -FLT_MAX, -FLT_MAX, -FLT_MAX);
    for (int i = beg + lane; i < end; i += 32) {
        int s = g_col[i];
        float4 a = ((const float4*)g_as1)[s];
        mx.x = fmaxf(mx.x, lrelu(a.x + ad.x));
        mx.y = fmaxf(mx.y, lrelu(a.y + ad.y));
        mx.z = fmaxf(mx.z, lrelu(a.z + ad.z));
        mx.w = fmaxf(mx.w, lrelu(a.w + ad.w));
    }
#pragma unroll
    for (int off = 16; off; off >>= 1) {
        mx.x = fmaxf(mx.x, __shfl_xor_sync(0xffffffffu, mx.x, off));
        mx.y = fmaxf(mx.y, __shfl_xor_sync(0xffffffffu, mx.y, off));
        mx.z = fmaxf(mx.z, __shfl_xor_sync(0xffffffffu, mx.z, off));
        mx.w = fmaxf(mx.w, __shfl_xor_sync(0xffffffffu, mx.w, off));
    }

    int hd = lane >> 3;
    float mh  = (hd == 0) ? mx.x : (hd == 1) ? mx.y : (hd == 2) ? mx.z : mx.w;
    float adh = (hd == 0) ? ad.x : (hd == 1) ? ad.y : (hd == 2) ? ad.z : ad.w;

    float ws = 0.f;
    float4 acc = make_float4(0.f, 0.f, 0.f, 0.f);
    for (int i = beg; i < end; i++) {
        int s = g_col[i];
        float a = g_as1[s * 4 + hd];
        float wt = __expf(lrelu(a + adh) - mh);
        ws += wt;
        uint2 raw = ((const uint2*)g_h1)[s * 32 + lane];   // 4 halves
        float2 f01 = __half22float2(*reinterpret_cast<__half2*>(&raw.x));
        float2 f23 = __half22float2(*reinterpret_cast<__half2*>(&raw.y));
        acc.x += wt * f01.x;
        acc.y += wt * f01.y;
        acc.z += wt * f23.x;
        acc.w += wt * f23.y;
    }
    float inv = 1.f / (ws + 1e-16f);
    float4 bv = ((const float4*)b1)[lane];
    float4 o;
    o.x = elu(acc.x * inv + bv.x);
    o.y = elu(acc.y * inv + bv.y);
    o.z = elu(acc.z * inv + bv.z);
    o.w = elu(acc.w * inv + bv.w);
    ((float4*)g_agg1)[w * 32 + lane] = o;
}

// ---------------- fused attention + aggregation, layer 2 (1 head) -----------
__global__ void k_node2(const float* __restrict__ b2, float* __restrict__ out) {
    int w = (blockIdx.x * blockDim.x + threadIdx.x) >> 5;
    int lane = threadIdx.x & 31;
    if (w >= NN) return;
    int beg = g_rowptr[w], end = g_rowptr[w + 1];

    float adv = g_ad2[w];

    float mx = -FLT_MAX;
    for (int i = beg + lane; i < end; i += 32) {
        int s = g_col[i];
        mx = fmaxf(mx, lrelu(g_as2[s] + adv));
    }
#pragma unroll
    for (int off = 16; off; off >>= 1)
        mx = fmaxf(mx, __shfl_xor_sync(0xffffffffu, mx, off));

    float ws = 0.f;
    float4 acc = make_float4(0.f, 0.f, 0.f, 0.f);
    for (int i = beg; i < end; i++) {
        int s = g_col[i];
        float wt = __expf(lrelu(g_as2[s] + adv) - mx);
        ws += wt;
        uint2 raw = ((const uint2*)g_h2)[s * 32 + lane];
        float2 f01 = __half22float2(*reinterpret_cast<__half2*>(&raw.x));
        float2 f23 = __half22float2(*reinterpret_cast<__half2*>(&raw.y));
        acc.x += wt * f01.x;
        acc.y += wt * f01.y;
        acc.z += wt * f23.x;
        acc.w += wt * f23.y;
    }
    float inv = 1.f / (ws + 1e-16f);
    float4 bv = ((const float4*)b2)[lane];
    float4 o;
    o.x = elu(acc.x * inv + bv.x);
    o.y = elu(acc.y * inv + bv.y);
    o.z = elu(acc.z * inv + bv.z);
    o.w = elu(acc.w * inv + bv.w);
    ((float4*)out)[w * 32 + lane] = o;
}

// ---------------- host launch ------------------------------------------------
extern "C" void kernel_launch(void* const* d_in, const int* in_sizes, int n_in,
                              void* d_out, int out_size) {
    const float* x    = (const float*)d_in[0];
    const int*   ei   = (const int*)  d_in[1];
    const float* W1   = (const float*)d_in[2];
    const float* a_s1 = (const float*)d_in[3];
    const float* a_d1 = (const float*)d_in[4];
    const float* b1   = (const float*)d_in[5];
    const float* W2   = (const float*)d_in[6];
    const float* a_s2 = (const float*)d_in[7];
    const float* a_d2 = (const float*)d_in[8];
    const float* b2   = (const float*)d_in[9];
    float* out = (float*)d_out;

    const int EB = (ET + 255) / 256;
    const int NB = (NN + 255) / 256;
    const int WARPB = (NN * 32 + 255) / 256;

    // CSR build (shared by both layers)
    k_zero<<<NB, 256>>>();
    k_count<<<EB, 256>>>(ei);
    k_scan_part<<<SCAN_B, 1024>>>();
    k_scan_top<<<1, 32>>>();
    k_rowptr<<<NB, 256>>>();
    k_fill<<<EB, 256>>>(ei);

    // layer 1
    k_gemm<0><<<(NN + 63) / 64, 256>>>(x, W1, a_s1, a_d1);
    k_node1<<<WARPB, 256>>>(b1);

    // layer 2
    k_gemm<1><<<(NN + 63) / 64, 256>>>(nullptr, W2, a_s2, a_d2);
    k_node2<<<WARPB, 256>>>(b2, out);
}

// round 9
// speedup vs baseline: 1.3654x; 1.0422x over previous
#include <cuda_runtime.h>
#include <cuda_fp16.h>
#include <math.h>
#include <float.h>

#define NN 50000
#define EE 800000
#define ET (EE + NN)
#define SCAN_B 49   // ceil(50000/1024)

// ---------------- scratch ---------------------------------------------------
__device__ __half g_h1[NN * 128];
__device__ __half g_h2[NN * 128];
__device__ float  g_agg1[NN * 128];
__device__ float  g_as1[NN * 4];
__device__ float  g_ad1[NN * 4];
__device__ float  g_as2[NN];
__device__ float  g_ad2[NN];
__device__ int    g_deg[NN];
__device__ int    g_scan[SCAN_B * 1024];
__device__ int    g_bsum[SCAN_B];
__device__ int    g_boff[SCAN_B];
__device__ int    g_rowptr[NN + 1];
__device__ int    g_fill[NN];
__device__ int    g_col[ET];
__device__ int    g_dst[ET];
__device__ float  g_w1[ET * 4];   // per-edge exp weights, layer1 (4 heads)
__device__ float  g_w2[ET];       // layer2 (1 head)

__device__ __forceinline__ float lrelu(float x) { return x > 0.f ? x : 0.2f * x; }
__device__ __forceinline__ float elu(float x)   { return x > 0.f ? x : expm1f(x); }

// ---------------- CSR build -------------------------------------------------
__global__ void k_zero() {
    int i = blockIdx.x * blockDim.x + threadIdx.x;
    if (i < NN) g_deg[i] = 0;
}

__global__ void k_count(const int* __restrict__ ei) {
    int e = blockIdx.x * blockDim.x + threadIdx.x;
    if (e >= ET) return;
    int d = (e < EE) ? ei[EE + e] : (e - EE);
    atomicAdd(&g_deg[d], 1);
}

__global__ void k_scan_part() {
    __shared__ int sh[1024];
    int tid = threadIdx.x;
    int i = blockIdx.x * 1024 + tid;
    int v = (i < NN) ? g_deg[i] : 0;
    sh[tid] = v;
    __syncthreads();
#pragma unroll
    for (int off = 1; off < 1024; off <<= 1) {
        int t = (tid >= off) ? sh[tid - off] : 0;
        __syncthreads();
        sh[tid] += t;
        __syncthreads();
    }
    g_scan[i] = sh[tid];
    if (tid == 1023) g_bsum[blockIdx.x] = sh[tid];
}

__global__ void k_scan_top() {
    if (threadIdx.x == 0) {
        int s = 0;
        for (int b = 0; b < SCAN_B; b++) { int t = g_bsum[b]; g_boff[b] = s; s += t; }
    }
}

__global__ void k_rowptr() {
    int i = blockIdx.x * blockDim.x + threadIdx.x;
    if (i >= NN) return;
    int incl = g_scan[i] + g_boff[i >> 10];
    g_rowptr[i + 1] = incl;
    g_fill[i] = incl - g_deg[i];
    if (i == 0) g_rowptr[0] = 0;
}

__global__ void k_fill(const int* __restrict__ ei) {
    int e = blockIdx.x * blockDim.x + threadIdx.x;
    if (e >= ET) return;
    int s, d;
    if (e < EE) { s = ei[e]; d = ei[EE + e]; } else { s = e - EE; d = s; }
    int pos = atomicAdd(&g_fill[d], 1);
    g_col[pos] = s;
    g_dst[pos] = d;
}

// ---------------- GEMM [NN,128]@[128,128], scalar FFMA, fp16 H store --------
template <int LAYER>
__global__ void __launch_bounds__(256) k_gemm(const float* __restrict__ Xext,
                       const float* __restrict__ W,
                       const float* __restrict__ asrc,
                       const float* __restrict__ adst) {
    const float* __restrict__ X = (LAYER == 0) ? Xext : g_agg1;
    __half* __restrict__ H = (LAYER == 0) ? g_h1 : g_h2;

    __shared__ float xs[64][128];
    int row0 = blockIdx.x * 64;

    for (int i = threadIdx.x; i < 64 * 32; i += 256) {
        int r = i >> 5, c4 = i & 31;
        int row = row0 + r;
        float4 v = make_float4(0.f, 0.f, 0.f, 0.f);
        if (row < NN) v = ((const float4*)X)[row * 32 + c4];
        *(float4*)(&xs[r][c4 * 4]) = v;
    }
    __syncthreads();

    int tc = threadIdx.x & 31;
    int tr = threadIdx.x >> 5;
    float acc[8][4];
#pragma unroll
    for (int r = 0; r < 8; r++)
#pragma unroll
        for (int j = 0; j < 4; j++) acc[r][j] = 0.f;

#pragma unroll 8
    for (int k = 0; k < 128; k++) {
        float4 w = ((const float4*)W)[k * 32 + tc];
#pragma unroll
        for (int r = 0; r < 8; r++) {
            float xv = xs[tr * 8 + r][k];
            acc[r][0] += xv * w.x;
            acc[r][1] += xv * w.y;
            acc[r][2] += xv * w.z;
            acc[r][3] += xv * w.w;
        }
    }

    float4 av = ((const float4*)asrc)[tc];
    float4 dv = ((const float4*)adst)[tc];

#pragma unroll
    for (int r = 0; r < 8; r++) {
        int row = row0 + tr * 8 + r;
        if (row >= NN) continue;
        __half2 p0 = __floats2half2_rn(acc[r][0], acc[r][1]);
        __half2 p1 = __floats2half2_rn(acc[r][2], acc[r][3]);
        ((__half2*)H)[row * 64 + tc * 2]     = p0;
        ((__half2*)H)[row * 64 + tc * 2 + 1] = p1;

        float s = acc[r][0] * av.x + acc[r][1] * av.y + acc[r][2] * av.z + acc[r][3] * av.w;
        float d = acc[r][0] * dv.x + acc[r][1] * dv.y + acc[r][2] * dv.z + acc[r][3] * dv.w;
        if (LAYER == 0) {
#pragma unroll
            for (int off = 4; off; off >>= 1) {
                s += __shfl_xor_sync(0xffffffffu, s, off);
                d += __shfl_xor_sync(0xffffffffu, d, off);
            }
            if ((tc & 7) == 0) {
                g_as1[row * 4 + (tc >> 3)] = s;
                g_ad1[row * 4 + (tc >> 3)] = d;
            }
        } else {
#pragma unroll
            for (int off = 16; off; off >>= 1) {
                s += __shfl_xor_sync(0xffffffffu, s, off);
                d += __shfl_xor_sync(0xffffffffu, d, off);
            }
            if (tc == 0) { g_as2[row] = s; g_ad2[row] = d; }
        }
    }
}

// ---------------- edge-parallel exp weights (no max shift) ------------------
__global__ void k_edgew1() {
    int e = blockIdx.x * blockDim.x + threadIdx.x;
    if (e >= ET) return;
    int s = g_col[e];
    int d = g_dst[e];
    float4 a = ((const float4*)g_as1)[s];
    float4 b = ((const float4*)g_ad1)[d];
    float4 w;
    w.x = __expf(lrelu(a.x + b.x));
    w.y = __expf(lrelu(a.y + b.y));
    w.z = __expf(lrelu(a.z + b.z));
    w.w = __expf(lrelu(a.w + b.w));
    ((float4*)g_w1)[e] = w;
}

__global__ void k_edgew2() {
    int e = blockIdx.x * blockDim.x + threadIdx.x;
    if (e >= ET) return;
    int s = g_col[e];
    int d = g_dst[e];
    g_w2[e] = __expf(lrelu(g_as2[s] + g_ad2[d]));
}

// ---------------- node aggregation, layer 1 (4 heads) -----------------------
// warp per node; lane owns 4 channels (head = lane>>3); 4x unrolled gathers
__global__ void k_node1(const float* __restrict__ b1) {
    int w = (blockIdx.x * blockDim.x + threadIdx.x) >> 5;
    int lane = threadIdx.x & 31;
    if (w >= NN) return;
    int beg = g_rowptr[w], end = g_rowptr[w + 1];
    int hd = lane >> 3;

    float ws = 0.f;
    float4 acc = make_float4(0.f, 0.f, 0.f, 0.f);

    int i = beg;
    for (; i + 4 <= end; i += 4) {
        int s0 = g_col[i], s1 = g_col[i + 1], s2 = g_col[i + 2], s3 = g_col[i + 3];
        float4 w0 = ((const float4*)g_w1)[i];
        float4 w1 = ((const float4*)g_w1)[i + 1];
        float4 w2 = ((const float4*)g_w1)[i + 2];
        float4 w3 = ((const float4*)g_w1)[i + 3];
        uint2 r0 = ((const uint2*)g_h1)[s0 * 32 + lane];
        uint2 r1 = ((const uint2*)g_h1)[s1 * 32 + lane];
        uint2 r2 = ((const uint2*)g_h1)[s2 * 32 + lane];
        uint2 r3 = ((const uint2*)g_h1)[s3 * 32 + lane];
        float wh0 = (hd == 0) ? w0.x : (hd == 1) ? w0.y : (hd == 2) ? w0.z : w0.w;
        float wh1 = (hd == 0) ? w1.x : (hd == 1) ? w1.y : (hd == 2) ? w1.z : w1.w;
        float wh2 = (hd == 0) ? w2.x : (hd == 1) ? w2.y : (hd == 2) ? w2.z : w2.w;
        float wh3 = (hd == 0) ? w3.x : (hd == 1) ? w3.y : (hd == 2) ? w3.z : w3.w;
        ws += wh0 + wh1 + wh2 + wh3;
        float2 a0 = __half22float2(*reinterpret_cast<__half2*>(&r0.x));
        float2 b0 = __half22float2(*reinterpret_cast<__half2*>(&r0.y));
        float2 a1 = __half22float2(*reinterpret_cast<__half2*>(&r1.x));
        float2 b1v = __half22float2(*reinterpret_cast<__half2*>(&r1.y));
        float2 a2 = __half22float2(*reinterpret_cast<__half2*>(&r2.x));
        float2 b2v = __half22float2(*reinterpret_cast<__half2*>(&r2.y));
        float2 a3 = __half22float2(*reinterpret_cast<__half2*>(&r3.x));
        float2 b3v = __half22float2(*reinterpret_cast<__half2*>(&r3.y));
        acc.x += wh0 * a0.x + wh1 * a1.x + wh2 * a2.x + wh3 * a3.x;
        acc.y += wh0 * a0.y + wh1 * a1.y + wh2 * a2.y + wh3 * a3.y;
        acc.z += wh0 * b0.x + wh1 * b1v.x + wh2 * b2v.x + wh3 * b3v.x;
        acc.w += wh0 * b0.y + wh1 * b1v.y + wh2 * b2v.y + wh3 * b3v.y;
    }
    for (; i < end; i++) {
        int s = g_col[i];
        float4 wv = ((const float4*)g_w1)[i];
        float wh = (hd == 0) ? wv.x : (hd == 1) ? wv.y : (hd == 2) ? wv.z : wv.w;
        ws += wh;
        uint2 raw = ((const uint2*)g_h1)[s * 32 + lane];
        float2 f01 = __half22float2(*reinterpret_cast<__half2*>(&raw.x));
        float2 f23 = __half22float2(*reinterpret_cast<__half2*>(&raw.y));
        acc.x += wh * f01.x;
        acc.y += wh * f01.y;
        acc.z += wh * f23.x;
        acc.w += wh * f23.y;
    }

    float inv = 1.f / (ws + 1e-16f);
    float4 bv = ((const float4*)b1)[lane];
    float4 o;
    o.x = elu(acc.x * inv + bv.x);
    o.y = elu(acc.y * inv + bv.y);
    o.z = elu(acc.z * inv + bv.z);
    o.w = elu(acc.w * inv + bv.w);
    ((float4*)g_agg1)[w * 32 + lane] = o;
}

// ---------------- node aggregation, layer 2 (1 head) ------------------------
__global__ void k_node2(const float* __restrict__ b2, float* __restrict__ out) {
    int w = (blockIdx.x * blockDim.x + threadIdx.x) >> 5;
    int lane = threadIdx.x & 31;
    if (w >= NN) return;
    int beg = g_rowptr[w], end = g_rowptr[w + 1];

    float ws = 0.f;
    float4 acc = make_float4(0.f, 0.f, 0.f, 0.f);

    int i = beg;
    for (; i + 4 <= end; i += 4) {
        int s0 = g_col[i], s1 = g_col[i + 1], s2 = g_col[i + 2], s3 = g_col[i + 3];
        float w0 = g_w2[i], w1 = g_w2[i + 1], w2 = g_w2[i + 2], w3 = g_w2[i + 3];
        uint2 r0 = ((const uint2*)g_h2)[s0 * 32 + lane];
        uint2 r1 = ((const uint2*)g_h2)[s1 * 32 + lane];
        uint2 r2 = ((const uint2*)g_h2)[s2 * 32 + lane];
        uint2 r3 = ((const uint2*)g_h2)[s3 * 32 + lane];
        ws += w0 + w1 + w2 + w3;
        float2 a0 = __half22float2(*reinterpret_cast<__half2*>(&r0.x));
        float2 b0 = __half22float2(*reinterpret_cast<__half2*>(&r0.y));
        float2 a1 = __half22float2(*reinterpret_cast<__half2*>(&r1.x));
        float2 b1v = __half22float2(*reinterpret_cast<__half2*>(&r1.y));
        float2 a2 = __half22float2(*reinterpret_cast<__half2*>(&r2.x));
        float2 b2v = __half22float2(*reinterpret_cast<__half2*>(&r2.y));
        float2 a3 = __half22float2(*reinterpret_cast<__half2*>(&r3.x));
        float2 b3v = __half22float2(*reinterpret_cast<__half2*>(&r3.y));
        acc.x += w0 * a0.x + w1 * a1.x + w2 * a2.x + w3 * a3.x;
        acc.y += w0 * a0.y + w1 * a1.y + w2 * a2.y + w3 * a3.y;
        acc.z += w0 * b0.x + w1 * b1v.x + w2 * b2v.x + w3 * b3v.x;
        acc.w += w0 * b0.y + w1 * b1v.y + w2 * b2v.y + w3 * b3v.y;
    }
    for (; i < end; i++) {
        int s = g_col[i];
        float wv = g_w2[i];
        ws += wv;
        uint2 raw = ((const uint2*)g_h2)[s * 32 + lane];
        float2 f01 = __half22float2(*reinterpret_cast<__half2*>(&raw.x));
        float2 f23 = __half22float2(*reinterpret_cast<__half2*>(&raw.y));
        acc.x += wv * f01.x;
        acc.y += wv * f01.y;
        acc.z += wv * f23.x;
        acc.w += wv * f23.y;
    }

    float inv = 1.f / (ws + 1e-16f);
    float4 bv = ((const float4*)b2)[lane];
    float4 o;
    o.x = elu(acc.x * inv + bv.x);
    o.y = elu(acc.y * inv + bv.y);
    o.z = elu(acc.z * inv + bv.z);
    o.w = elu(acc.w * inv + bv.w);
    ((float4*)out)[w * 32 + lane] = o;
}

// ---------------- host launch ------------------------------------------------
extern "C" void kernel_launch(void* const* d_in, const int* in_sizes, int n_in,
                              void* d_out, int out_size) {
    const float* x    = (const float*)d_in[0];
    const int*   ei   = (const int*)  d_in[1];
    const float* W1   = (const float*)d_in[2];
    const float* a_s1 = (const float*)d_in[3];
    const float* a_d1 = (const float*)d_in[4];
    const float* b1   = (const float*)d_in[5];
    const float* W2   = (const float*)d_in[6];
    const float* a_s2 = (const float*)d_in[7];
    const float* a_d2 = (const float*)d_in[8];
    const float* b2   = (const float*)d_in[9];
    float* out = (float*)d_out;

    const int EB = (ET + 255) / 256;
    const int NB = (NN + 255) / 256;
    const int WARPB = (NN * 32 + 255) / 256;

    // CSR build (shared by both layers)
    k_zero<<<NB, 256>>>();
    k_count<<<EB, 256>>>(ei);
    k_scan_part<<<SCAN_B, 1024>>>();
    k_scan_top<<<1, 32>>>();
    k_rowptr<<<NB, 256>>>();
    k_fill<<<EB, 256>>>(ei);

    // layer 1
    k_gemm<0><<<(NN + 63) / 64, 256>>>(x, W1, a_s1, a_d1);
    k_edgew1<<<EB, 256>>>();
    k_node1<<<WARPB, 256>>>(b1);

    // layer 2
    k_gemm<1><<<(NN + 63) / 64, 256>>>(nullptr, W2, a_s2, a_d2);
    k_edgew2<<<EB, 256>>>();
    k_node2<<<WARPB, 256>>>(b2, out);
}